// round 10
// baseline (speedup 1.0000x reference)
#include <cuda_runtime.h>
#include <cuda_bf16.h>
#include <cstdint>

// LengthRegulator: out[b, t, :] = phoneme[b, tok(b,t), :]
// tok(b,t) = searchsorted_right(inclusive_cumsum(durations[b,:]), t), clip N-1.
// Shapes (fixed): B=16, N=256, D=512, T=2048. float32.
//
// Two-kernel split:
//  1) idx_kernel: tiny, computes tok[b][t] map into __device__ scratch.
//  2) gather_kernel: one float4 per thread, no loops/barriers/smem.
//     4.19M independent LDG->STG pairs = maximal memory-level parallelism.

#define LR_B 16
#define LR_N 256
#define LR_D 512
#define LR_T 2048
#define VPF 128                        // float4 per frame (D*4/16)

__device__ int g_tok[LR_B * LR_T];     // 128KB frame->token map

__global__ __launch_bounds__(256)
void idx_kernel(const int* __restrict__ durations)
{
    __shared__ int s_ends[LR_N];
    const int b = blockIdx.x;
    const int tid = threadIdx.x;

    // warp 0: shuffle scan of durations[b,:]
    if (tid < 32) {
        const int lane = tid;
        const int4* drow = (const int4*)(durations + b * LR_N);
        int4 a = drow[lane * 2 + 0];
        int4 c = drow[lane * 2 + 1];
        int e0 = a.x;
        int e1 = e0 + a.y;
        int e2 = e1 + a.z;
        int e3 = e2 + a.w;
        int e4 = e3 + c.x;
        int e5 = e4 + c.y;
        int e6 = e5 + c.z;
        int e7 = e6 + c.w;
        int x = e7;
        #pragma unroll
        for (int off = 1; off < 32; off <<= 1) {
            int y = __shfl_up_sync(0xffffffffu, x, off);
            if (lane >= off) x += y;
        }
        const int excl = x - e7;
        s_ends[lane * 8 + 0] = e0 + excl;
        s_ends[lane * 8 + 1] = e1 + excl;
        s_ends[lane * 8 + 2] = e2 + excl;
        s_ends[lane * 8 + 3] = e3 + excl;
        s_ends[lane * 8 + 4] = e4 + excl;
        s_ends[lane * 8 + 5] = e5 + excl;
        s_ends[lane * 8 + 6] = e6 + excl;
        s_ends[lane * 8 + 7] = e7 + excl;
    }
    __syncthreads();

    // each thread: 8 frames, binary search (first n with ends[n] > t)
    #pragma unroll
    for (int j = 0; j < LR_T / 256; ++j) {
        const int t = j * 256 + tid;
        int lo = 0, hi = LR_N;
        #pragma unroll
        for (int it = 0; it < 9; ++it) {
            if (lo < hi) {
                int mid = (lo + hi) >> 1;
                if (s_ends[mid] > t) hi = mid; else lo = mid + 1;
            }
        }
        g_tok[b * LR_T + t] = (lo < LR_N) ? lo : (LR_N - 1);
    }
}

__global__ __launch_bounds__(256)
void gather_kernel(const float4* __restrict__ phoneme4,
                   float4* __restrict__ out4)
{
    // one float4 per thread; all divisors are powers of two
    const unsigned flat = blockIdx.x * 256u + threadIdx.x;   // < B*T*VPF = 4.19M
    const unsigned b = flat >> 18;                            // / (T*VPF)
    const unsigned rem = flat & ((LR_T * VPF) - 1);
    const unsigned t = rem >> 7;                              // / VPF
    const unsigned d = rem & (VPF - 1);

    const int tok = __ldg(&g_tok[b * LR_T + t]);              // warp-broadcast
    out4[flat] = phoneme4[((size_t)b * LR_N + tok) * VPF + d];
}

extern "C" void kernel_launch(void* const* d_in, const int* in_sizes, int n_in,
                              void* d_out, int out_size)
{
    const float4* phoneme4  = (const float4*)d_in[0];   // (B, N, D) f32
    const int*    durations = (const int*)d_in[1];      // (B, N) i32
    float4*       out4      = (float4*)d_out;           // (B, T, D) f32

    idx_kernel<<<LR_B, 256>>>(durations);
    const unsigned total4 = LR_B * LR_T * VPF;          // 4,194,304
    gather_kernel<<<total4 / 256, 256>>>(phoneme4, out4);
}

// round 11
// speedup vs baseline: 1.4341x; 1.4341x over previous
#include <cuda_runtime.h>
#include <cuda_bf16.h>

// LengthRegulator: out[b, t, :] = phoneme[b, tok(b,t), :]
// tok(b,t) = searchsorted_right(inclusive_cumsum(durations[b,:]), t), clip N-1.
// Shapes (fixed): B=16, N=256, D=512, T=2048. float32.
//
// Champion geometry (R2/R7): 1024 blocks x 256 threads, 32 frames/block.
// Warp-0 shuffle-scan preamble (1 barrier), unrolled coalesced copy,
// streaming (__stcs) stores on the 67MB output.

#define LR_B 16
#define LR_N 256
#define LR_D 512
#define LR_T 2048
#define FRAMES_PER_BLOCK 32
#define THREADS 256
#define VEC_PER_FRAME (LR_D / 4)   // 128 float4 per frame

__global__ __launch_bounds__(THREADS)
void length_regulator_kernel(const float4* __restrict__ phoneme4,
                             const int* __restrict__ durations,
                             float4* __restrict__ out4)
{
    const int b = blockIdx.y;
    const int frame_base = blockIdx.x * FRAMES_PER_BLOCK;
    const int tid = threadIdx.x;

    __shared__ int s_ends[LR_N];
    __shared__ int s_tok[FRAMES_PER_BLOCK];

    // Warp 0: shuffle scan (lane owns durations[8L..8L+7]) + binary search.
    if (tid < 32) {
        const int lane = tid;
        const int4* drow = (const int4*)(durations + b * LR_N);
        int4 a = drow[lane * 2 + 0];
        int4 c = drow[lane * 2 + 1];
        int e0 = a.x;
        int e1 = e0 + a.y;
        int e2 = e1 + a.z;
        int e3 = e2 + a.w;
        int e4 = e3 + c.x;
        int e5 = e4 + c.y;
        int e6 = e5 + c.z;
        int e7 = e6 + c.w;
        int x = e7;
        #pragma unroll
        for (int off = 1; off < 32; off <<= 1) {
            int y = __shfl_up_sync(0xffffffffu, x, off);
            if (lane >= off) x += y;
        }
        const int excl = x - e7;
        s_ends[lane * 8 + 0] = e0 + excl;
        s_ends[lane * 8 + 1] = e1 + excl;
        s_ends[lane * 8 + 2] = e2 + excl;
        s_ends[lane * 8 + 3] = e3 + excl;
        s_ends[lane * 8 + 4] = e4 + excl;
        s_ends[lane * 8 + 5] = e5 + excl;
        s_ends[lane * 8 + 6] = e6 + excl;
        s_ends[lane * 8 + 7] = e7 + excl;
        __syncwarp();

        // lower-bound: first n with ends[n] > t (9 steps for N=256)
        const int t = frame_base + lane;
        int lo = 0, hi = LR_N;
        #pragma unroll
        for (int it = 0; it < 9; ++it) {
            if (lo < hi) {
                int mid = (lo + hi) >> 1;
                if (s_ends[mid] > t) hi = mid; else lo = mid + 1;
            }
        }
        s_tok[lane] = (lo < LR_N) ? lo : (LR_N - 1);
    }
    __syncthreads();

    // Copy: 32 frames * 128 float4, coalesced; streaming stores.
    // Each thread handles a fixed column pair pattern: iteration i covers
    // frame f = i>>7 at column i&127 (as in R2), with tok loads hoisted by
    // full unrolling.
    const float4* __restrict__ ph_b  = phoneme4 + (size_t)b * LR_N * VEC_PER_FRAME;
    float4* __restrict__       out_b = out4 + ((size_t)b * LR_T + frame_base) * VEC_PER_FRAME;

    #pragma unroll
    for (int i = tid; i < FRAMES_PER_BLOCK * VEC_PER_FRAME; i += THREADS) {
        const int f   = i >> 7;              // i / 128
        const int off = i & (VEC_PER_FRAME - 1);
        const float4 v = ph_b[s_tok[f] * VEC_PER_FRAME + off];
        __stcs(&out_b[i], v);                // streaming store (evict-first)
    }
}

extern "C" void kernel_launch(void* const* d_in, const int* in_sizes, int n_in,
                              void* d_out, int out_size)
{
    const float4* phoneme4  = (const float4*)d_in[0];   // (B, N, D) f32
    const int*    durations = (const int*)d_in[1];      // (B, N) i32
    float4*       out4      = (float4*)d_out;           // (B, T, D) f32

    dim3 grid(LR_T / FRAMES_PER_BLOCK, LR_B);  // (64, 16) = 1024 blocks
    length_regulator_kernel<<<grid, THREADS>>>(phoneme4, durations, out4);
}